// round 5
// baseline (speedup 1.0000x reference)
#include <cuda_runtime.h>
#include <math.h>

#define SEQ   2048
#define EMB   1024
#define HID   2048
#define VOCAB 50257
#define WSTRIDE (EMB + HID)   // 3072, row stride of W_i2h

// ---------------- scratch (device globals: allocation-free rule) ----------
__device__ __align__(16) float g_X[SEQ * HID];   // 16 MB: X[t][r] = W_e@e_t + b
__device__ __align__(16) float g_h[2][HID];      // double-buffered hidden state
#define NCTA 128
__device__ unsigned g_flag[NCTA];                // monotonic per-CTA step flags
__device__ int g_tok64 = 0;

// ---------------- memory-order helpers -------------------------------------
__device__ __forceinline__ unsigned ld_relaxed(const unsigned* p) {
    unsigned v;
    asm volatile("ld.relaxed.gpu.global.u32 %0, [%1];" : "=r"(v) : "l"(p) : "memory");
    return v;
}
__device__ __forceinline__ void st_release(unsigned* p, unsigned v) {
    asm volatile("st.release.gpu.global.u32 [%0], %1;" :: "l"(p), "r"(v) : "memory");
}
__device__ __forceinline__ void fence_acq() {
    asm volatile("fence.acq_rel.gpu;" ::: "memory");
}

// ---------------- per-launch reset (graph replays reuse device globals) ---
__global__ void reset_kernel() {
    if (threadIdx.x < NCTA) g_flag[threadIdx.x] = 0;
}

// ---------------- token dtype detection ----------------------------------
__global__ void detect_tok_kernel(const int* __restrict__ p) {
    __shared__ int bad;
    if (threadIdx.x == 0) bad = 0;
    __syncthreads();
    int mybad = 0;
    for (int i = threadIdx.x; i < SEQ / 2; i += blockDim.x) {
        int lo = p[2 * i];
        int hi = p[2 * i + 1];
        if (hi != 0 || lo < 0 || lo >= VOCAB) mybad = 1;
    }
    if (mybad) atomicOr(&bad, 1);
    __syncthreads();
    if (threadIdx.x == 0) g_tok64 = bad ? 0 : 1;
}

// ---------------- X = E @ W_e^T + b  (gathered GEMM) ----------------------
#define BM 64
#define BN 64
#define BK 16

__global__ void gemm_x_kernel(const int* __restrict__ toks,
                              const float* __restrict__ emb,
                              const float* __restrict__ Wi2h,
                              const float* __restrict__ bias) {
    __shared__ __align__(16) float As[BK][BM + 4];
    __shared__ __align__(16) float Bs[BK][BN + 4];
    __shared__ int stok[BM];

    const int tid = threadIdx.x;           // 256 threads
    const int t0 = blockIdx.y * BM;        // token (M) tile
    const int r0 = blockIdx.x * BN;        // hidden-row (N) tile
    const int tok64 = g_tok64;

    if (tid < BM) {
        int t = t0 + tid;
        stok[tid] = tok64 ? toks[2 * t] : toks[t];
    }
    __syncthreads();

    float acc[4][4] = {};
    const int tx = tid & 15;   // N
    const int ty = tid >> 4;   // M

    for (int kk = 0; kk < EMB; kk += BK) {
#pragma unroll
        for (int i = 0; i < 4; i++) {
            int idx = tid + i * 256;       // 0..1023
            int m = idx >> 4;
            int k = idx & 15;
            As[k][m] = emb[(size_t)stok[m] * EMB + kk + k];
            Bs[k][m] = Wi2h[(size_t)(r0 + m) * WSTRIDE + kk + k];  // W_e cols
        }
        __syncthreads();
#pragma unroll
        for (int k = 0; k < BK; k++) {
            float4 a4 = *(const float4*)&As[k][ty * 4];
            float4 b4 = *(const float4*)&Bs[k][tx * 4];
            float a[4] = {a4.x, a4.y, a4.z, a4.w};
            float b[4] = {b4.x, b4.y, b4.z, b4.w};
#pragma unroll
            for (int i = 0; i < 4; i++)
#pragma unroll
                for (int j = 0; j < 4; j++) acc[i][j] += a[i] * b[j];
        }
        __syncthreads();
    }

#pragma unroll
    for (int i = 0; i < 4; i++) {
        int t = t0 + ty * 4 + i;
#pragma unroll
        for (int j = 0; j < 4; j++) {
            int r = r0 + tx * 4 + j;
            g_X[(size_t)t * HID + r] = acc[i][j] + bias[r];
        }
    }
}

// ---------------- persistent recurrence kernel ----------------------------
#define ROWS_PER_CTA (HID / NCTA)  // 16
#define RTHREADS 512               // 16 warps: warp = (grp = w&3 rows, q = w>>2 slice)

__global__ void __launch_bounds__(RTHREADS, 1)
rnn_kernel(const float* __restrict__ Wi2h,
           const float* __restrict__ Wh2o,
           const float* __restrict__ bh2o,
           float* __restrict__ out) {
    __shared__ __align__(16) float sh[HID];   // staged h_{t-1}
    __shared__ float sred[64];

    const int tid = threadIdx.x;
    const int cta = blockIdx.x;
    const int r0  = cta * ROWS_PER_CTA;

    const int w = tid >> 5, l = tid & 31;
    const int grp = w & 3;   // rows r0 + 4*grp .. +3
    const int q   = w >> 2;  // h-slice [512q, 512(q+1))

    // ---- W_h slice into registers: 4 rows x 16 cols per lane (64 regs) ----
    float4 Wr[4][4];
#pragma unroll
    for (int rr = 0; rr < 4; rr++)
#pragma unroll
        for (int k = 0; k < 4; k++)
            Wr[rr][k] = *(const float4*)&Wi2h[
                (size_t)(r0 + 4 * grp + rr) * WSTRIDE + EMB
                + (q << 9) + (l << 2) + (k << 7)];

    for (int t = 0; t < SEQ; t++) {
        // prefetch this CTA's X[t] slice (hides L2 latency behind poll)
        float xv = 0.f;
        if (tid < ROWS_PER_CTA) xv = __ldcg(&g_X[(size_t)t * HID + r0 + tid]);

        if (t > 0) {
            // each warp polls the 8 flags of the CTAs producing its chunk
            {
                const unsigned tgt = (unsigned)t;
                for (;;) {
                    unsigned f = 0xffffffffu;
                    if (l < 8) f = ld_relaxed(&g_flag[(w << 3) + l]);
                    if (__all_sync(0xffffffffu, f >= tgt)) break;
                }
                fence_acq();
            }

            // stage distinct 128-float chunk w of h_{t-1} into SMEM
            const float* hprev = g_h[(t - 1) & 1];
            float4 ch = __ldcg((const float4*)&hprev[(w << 7) + (l << 2)]);
            *(float4*)&sh[(w << 7) + (l << 2)] = ch;
            __syncthreads();   // bar#1: full h staged

            // consume q-slice from SMEM
            const float4* sh4 = (const float4*)sh;
            float4 hv[4];
#pragma unroll
            for (int k = 0; k < 4; k++)
                hv[k] = sh4[(q << 7) + (k << 5) + l];

            float acc[4] = {0.f, 0.f, 0.f, 0.f};
#pragma unroll
            for (int k = 0; k < 4; k++)
#pragma unroll
                for (int rr = 0; rr < 4; rr++)
                    acc[rr] += Wr[rr][k].x * hv[k].x + Wr[rr][k].y * hv[k].y
                             + Wr[rr][k].z * hv[k].z + Wr[rr][k].w * hv[k].w;

#pragma unroll
            for (int rr = 0; rr < 4; rr++) {
                float v = acc[rr];
                v += __shfl_xor_sync(0xffffffffu, v, 16);
                v += __shfl_xor_sync(0xffffffffu, v, 8);
                v += __shfl_xor_sync(0xffffffffu, v, 4);
                v += __shfl_xor_sync(0xffffffffu, v, 2);
                v += __shfl_xor_sync(0xffffffffu, v, 1);
                if (l == 0) sred[w * 4 + rr] = v;
            }
            __syncthreads();   // bar#2: sred ready (also orders all reads < flag)

            if (tid < ROWS_PER_CTA) {
                int g = tid >> 2, rr = tid & 3;
                float v = xv;
#pragma unroll
                for (int qq = 0; qq < 4; qq++)
                    v += sred[((qq << 2) | g) * 4 + rr];
                g_h[t & 1][r0 + tid] = v;
            }
        } else {
            // h after first token: W_h @ 0 + X[0] = X[0]
            if (tid < ROWS_PER_CTA) g_h[0][r0 + tid] = xv;
        }

        // publish: h stores (lanes 0..15 of warp 0) -> syncwarp -> release flag
        if (w == 0) {
            __syncwarp();
            if (l == 0) st_release(&g_flag[cta], (unsigned)(t + 1));
        }
    }

    // readout: out = sigmoid(W_h2o @ h_final + b_h2o)
    if (cta == 0) {
        if (w == 0) {
            for (;;) {
                unsigned a = ld_relaxed(&g_flag[l]);
                unsigned b = ld_relaxed(&g_flag[32 + l]);
                unsigned c = ld_relaxed(&g_flag[64 + l]);
                unsigned d = ld_relaxed(&g_flag[96 + l]);
                unsigned m = min(min(a, b), min(c, d));
                if (__all_sync(0xffffffffu, m >= (unsigned)SEQ)) break;
            }
            fence_acq();
        }
        __syncthreads();
        const float* hf = g_h[(SEQ - 1) & 1];
        float s = 0.f;
        for (int j = tid; j < HID; j += RTHREADS) s += __ldcg(&hf[j]) * Wh2o[j];
#pragma unroll
        for (int o = 16; o > 0; o >>= 1) s += __shfl_xor_sync(0xffffffffu, s, o);
        __syncthreads();   // sred free for reuse
        if (l == 0) sred[w] = s;
        __syncthreads();
        if (tid == 0) {
            float tot = 0.f;
#pragma unroll
            for (int i = 0; i < RTHREADS / 32; i++) tot += sred[i];
            tot += bh2o[0];
            out[0] = 1.f / (1.f + expf(-tot));
        }
    }
}

// ---------------- launch ---------------------------------------------------
extern "C" void kernel_launch(void* const* d_in, const int* in_sizes, int n_in,
                              void* d_out, int out_size) {
    const int*   toks = (const int*)d_in[0];
    const float* emb  = (const float*)d_in[1];
    const float* Wi2h = (const float*)d_in[2];
    const float* bi2h = (const float*)d_in[3];
    const float* Wh2o = (const float*)d_in[4];
    const float* bh2o = (const float*)d_in[5];
    float* out = (float*)d_out;

    reset_kernel<<<1, 128>>>();
    detect_tok_kernel<<<1, 256>>>(toks);
    gemm_x_kernel<<<dim3(HID / BN, SEQ / BM), 256>>>(toks, emb, Wi2h, bi2h);
    rnn_kernel<<<NCTA, RTHREADS>>>(Wi2h, Wh2o, bh2o, out);
}

// round 6
// speedup vs baseline: 2.7366x; 2.7366x over previous
#include <cuda_runtime.h>
#include <math.h>

#define SEQ   2048
#define EMB   1024
#define HID   2048
#define VOCAB 50257
#define WSTRIDE (EMB + HID)   // 3072, row stride of W_i2h

#define NCTA 128
#define NREP 4

// ---------------- scratch (device globals: allocation-free rule) ----------
__device__ __align__(16) float g_X[SEQ * HID];        // 16 MB
__device__ __align__(16) float g_hrep[2][NREP][HID];  // replicated h, dbl-buffered
__device__ unsigned g_cnt;                            // monotonic arrival counter
__device__ unsigned g_epoch;                          // broadcast word
__device__ int g_tok64 = 0;

// ---------------- memory-order helpers -------------------------------------
__device__ __forceinline__ unsigned ld_relaxed(const unsigned* p) {
    unsigned v;
    asm volatile("ld.relaxed.gpu.global.u32 %0, [%1];" : "=r"(v) : "l"(p) : "memory");
    return v;
}
__device__ __forceinline__ unsigned atom_add_release(unsigned* p, unsigned v) {
    unsigned old;
    asm volatile("atom.release.gpu.global.add.u32 %0, [%1], %2;"
                 : "=r"(old) : "l"(p), "r"(v) : "memory");
    return old;
}
__device__ __forceinline__ void st_release(unsigned* p, unsigned v) {
    asm volatile("st.release.gpu.global.u32 [%0], %1;" :: "l"(p), "r"(v) : "memory");
}
__device__ __forceinline__ void fence_acq() {
    asm volatile("fence.acq_rel.gpu;" ::: "memory");
}

// ---------------- per-launch reset (graph replays reuse device globals) ---
__global__ void reset_kernel() {
    if (threadIdx.x == 0) { g_cnt = 0; g_epoch = 0; }
}

// ---------------- token dtype detection ----------------------------------
__global__ void detect_tok_kernel(const int* __restrict__ p) {
    __shared__ int bad;
    if (threadIdx.x == 0) bad = 0;
    __syncthreads();
    int mybad = 0;
    for (int i = threadIdx.x; i < SEQ / 2; i += blockDim.x) {
        int lo = p[2 * i];
        int hi = p[2 * i + 1];
        if (hi != 0 || lo < 0 || lo >= VOCAB) mybad = 1;
    }
    if (mybad) atomicOr(&bad, 1);
    __syncthreads();
    if (threadIdx.x == 0) g_tok64 = bad ? 0 : 1;
}

// ---------------- X = E @ W_e^T + b  (gathered GEMM) ----------------------
#define BM 64
#define BN 64
#define BK 16

__global__ void gemm_x_kernel(const int* __restrict__ toks,
                              const float* __restrict__ emb,
                              const float* __restrict__ Wi2h,
                              const float* __restrict__ bias) {
    __shared__ __align__(16) float As[BK][BM + 4];
    __shared__ __align__(16) float Bs[BK][BN + 4];
    __shared__ int stok[BM];

    const int tid = threadIdx.x;           // 256 threads
    const int t0 = blockIdx.y * BM;
    const int r0 = blockIdx.x * BN;
    const int tok64 = g_tok64;

    if (tid < BM) {
        int t = t0 + tid;
        stok[tid] = tok64 ? toks[2 * t] : toks[t];
    }
    __syncthreads();

    float acc[4][4] = {};
    const int tx = tid & 15;
    const int ty = tid >> 4;

    for (int kk = 0; kk < EMB; kk += BK) {
#pragma unroll
        for (int i = 0; i < 4; i++) {
            int idx = tid + i * 256;
            int m = idx >> 4;
            int k = idx & 15;
            As[k][m] = emb[(size_t)stok[m] * EMB + kk + k];
            Bs[k][m] = Wi2h[(size_t)(r0 + m) * WSTRIDE + kk + k];
        }
        __syncthreads();
#pragma unroll
        for (int k = 0; k < BK; k++) {
            float4 a4 = *(const float4*)&As[k][ty * 4];
            float4 b4 = *(const float4*)&Bs[k][tx * 4];
            float a[4] = {a4.x, a4.y, a4.z, a4.w};
            float b[4] = {b4.x, b4.y, b4.z, b4.w};
#pragma unroll
            for (int i = 0; i < 4; i++)
#pragma unroll
                for (int j = 0; j < 4; j++) acc[i][j] += a[i] * b[j];
        }
        __syncthreads();
    }

#pragma unroll
    for (int i = 0; i < 4; i++) {
        int t = t0 + ty * 4 + i;
#pragma unroll
        for (int j = 0; j < 4; j++) {
            int r = r0 + tx * 4 + j;
            g_X[(size_t)t * HID + r] = acc[i][j] + bias[r];
        }
    }
}

// ---------------- persistent recurrence kernel ----------------------------
#define ROWS_PER_CTA (HID / NCTA)  // 16
#define RTHREADS 512               // 16 warps

__global__ void __launch_bounds__(RTHREADS, 1)
rnn_kernel(const float* __restrict__ Wi2h,
           const float* __restrict__ Wh2o,
           const float* __restrict__ bh2o,
           float* __restrict__ out) {
    __shared__ __align__(16) float sh[HID];
    __shared__ float sred[64];

    const int tid = threadIdx.x;
    const int cta = blockIdx.x;
    const int r0  = cta * ROWS_PER_CTA;
    const int repl = cta & (NREP - 1);

    const int w = tid >> 5, l = tid & 31;
    const int grp = w & 3;   // rows r0 + 4*grp .. +3
    const int q   = w >> 2;  // h-slice [512q, 512(q+1))

    // ---- W_h slice into registers: 4 rows x 16 cols per lane (64 regs) ----
    float4 Wr[4][4];
#pragma unroll
    for (int rr = 0; rr < 4; rr++)
#pragma unroll
        for (int k = 0; k < 4; k++)
            Wr[rr][k] = *(const float4*)&Wi2h[
                (size_t)(r0 + 4 * grp + rr) * WSTRIDE + EMB
                + (q << 9) + (l << 2) + (k << 7)];

    for (int t = 0; t < SEQ; t++) {
        // prefetch this CTA's X[t] slice
        float xv = 0.f;
        if (tid < ROWS_PER_CTA) xv = __ldcg(&g_X[(size_t)t * HID + r0 + tid]);

        if (t > 0) {
            // warp 0 polls the single epoch word (same-address = 1 request/iter)
            if (w == 0) {
                const unsigned tgt = (unsigned)t;
                unsigned e;
                do { e = ld_relaxed(&g_epoch); }
                while (__any_sync(0xffffffffu, e < tgt));
                fence_acq();
            }
            __syncthreads();   // bar1: epoch reached, acquire ordering CTA-wide

            // stage distinct chunk w of h_{t-1} from this CTA's replica
            const float* hprev = g_hrep[(t - 1) & 1][repl];
            float4 ch = __ldcg((const float4*)&hprev[(w << 7) + (l << 2)]);
            *(float4*)&sh[(w << 7) + (l << 2)] = ch;
            __syncthreads();   // bar2: full h staged

            const float4* sh4 = (const float4*)sh;
            float4 hv[4];
#pragma unroll
            for (int k = 0; k < 4; k++)
                hv[k] = sh4[(q << 7) + (k << 5) + l];

            float acc[4] = {0.f, 0.f, 0.f, 0.f};
#pragma unroll
            for (int k = 0; k < 4; k++)
#pragma unroll
                for (int rr = 0; rr < 4; rr++)
                    acc[rr] += Wr[rr][k].x * hv[k].x + Wr[rr][k].y * hv[k].y
                             + Wr[rr][k].z * hv[k].z + Wr[rr][k].w * hv[k].w;

#pragma unroll
            for (int rr = 0; rr < 4; rr++) {
                float v = acc[rr];
                v += __shfl_xor_sync(0xffffffffu, v, 16);
                v += __shfl_xor_sync(0xffffffffu, v, 8);
                v += __shfl_xor_sync(0xffffffffu, v, 4);
                v += __shfl_xor_sync(0xffffffffu, v, 2);
                v += __shfl_xor_sync(0xffffffffu, v, 1);
                if (l == 0) sred[w * 4 + rr] = v;
            }
            __syncthreads();   // bar3: sred ready

            if (tid < ROWS_PER_CTA) {
                int g = tid >> 2, rr = tid & 3;
                float v = xv;
#pragma unroll
                for (int qq = 0; qq < 4; qq++)
                    v += sred[((qq << 2) | g) * 4 + rr];
#pragma unroll
                for (int r = 0; r < NREP; r++)
                    g_hrep[t & 1][r][r0 + tid] = v;
            }
        } else {
            // h after first token: W_h @ 0 + X[0] = X[0]
            if (tid < ROWS_PER_CTA) {
#pragma unroll
                for (int r = 0; r < NREP; r++)
                    g_hrep[0][r][r0 + tid] = xv;
            }
        }

        // arrive: h stores (lanes 0..15 of warp 0) -> syncwarp -> counter
        if (w == 0) {
            __syncwarp();
            if (l == 0) {
                unsigned prev = atom_add_release(&g_cnt, 1u);
                if (prev == (unsigned)NCTA * (t + 1) - 1u)
                    st_release(&g_epoch, (unsigned)(t + 1));
            }
        }
    }

    // readout: out = sigmoid(W_h2o @ h_final + b_h2o)
    if (cta == 0) {
        if (w == 0) {
            unsigned e;
            do { e = ld_relaxed(&g_epoch); }
            while (__any_sync(0xffffffffu, e < (unsigned)SEQ));
            fence_acq();
        }
        __syncthreads();
        const float* hf = g_hrep[(SEQ - 1) & 1][0];
        float s = 0.f;
        for (int j = tid; j < HID; j += RTHREADS) s += __ldcg(&hf[j]) * Wh2o[j];
#pragma unroll
        for (int o = 16; o > 0; o >>= 1) s += __shfl_xor_sync(0xffffffffu, s, o);
        __syncthreads();
        if (l == 0) sred[w] = s;
        __syncthreads();
        if (tid == 0) {
            float tot = 0.f;
#pragma unroll
            for (int i = 0; i < RTHREADS / 32; i++) tot += sred[i];
            tot += bh2o[0];
            out[0] = 1.f / (1.f + expf(-tot));
        }
    }
}

// ---------------- launch ---------------------------------------------------
extern "C" void kernel_launch(void* const* d_in, const int* in_sizes, int n_in,
                              void* d_out, int out_size) {
    const int*   toks = (const int*)d_in[0];
    const float* emb  = (const float*)d_in[1];
    const float* Wi2h = (const float*)d_in[2];
    const float* bi2h = (const float*)d_in[3];
    const float* Wh2o = (const float*)d_in[4];
    const float* bh2o = (const float*)d_in[5];
    float* out = (float*)d_out;

    reset_kernel<<<1, 32>>>();
    detect_tok_kernel<<<1, 256>>>(toks);
    gemm_x_kernel<<<dim3(HID / BN, SEQ / BM), 256>>>(toks, emb, Wi2h, bi2h);
    rnn_kernel<<<NCTA, RTHREADS>>>(Wi2h, Wh2o, bh2o, out);
}

// round 7
// speedup vs baseline: 3.1256x; 1.1421x over previous
#include <cuda_runtime.h>
#include <math.h>

#define SEQ   2048
#define EMB   1024
#define HID   2048
#define VOCAB 50257
#define WSTRIDE (EMB + HID)   // 3072, row stride of W_i2h

#define NCTA 128
#define NREP 4

// ---------------- scratch (device globals: allocation-free rule) ----------
__device__ __align__(16) float g_X[SEQ * HID];        // 16 MB
__device__ __align__(16) float g_hrep[2][NREP][HID];  // replicated h, dbl-buffered
__device__ unsigned g_cnt;                            // monotonic arrival counter
__device__ int g_tok64 = 0;

// ---------------- memory-order / packed-math helpers ----------------------
__device__ __forceinline__ unsigned ld_relaxed(const unsigned* p) {
    unsigned v;
    asm volatile("ld.relaxed.gpu.global.u32 %0, [%1];" : "=r"(v) : "l"(p) : "memory");
    return v;
}
__device__ __forceinline__ void red_add_release(unsigned* p, unsigned v) {
    asm volatile("red.release.gpu.global.add.u32 [%0], %1;" :: "l"(p), "r"(v) : "memory");
}
__device__ __forceinline__ void fence_acq() {
    asm volatile("fence.acq_rel.gpu;" ::: "memory");
}
__device__ __forceinline__ unsigned long long pack2(float lo, float hi) {
    unsigned long long r;
    asm("mov.b64 %0, {%1, %2};" : "=l"(r) : "f"(lo), "f"(hi));
    return r;
}
__device__ __forceinline__ void unpack2(float& lo, float& hi, unsigned long long v) {
    asm("mov.b64 {%0, %1}, %2;" : "=f"(lo), "=f"(hi) : "l"(v));
}
__device__ __forceinline__ void ffma2(unsigned long long& acc,
                                      unsigned long long a, unsigned long long b) {
    asm("fma.rn.f32x2 %0, %1, %2, %0;" : "+l"(acc) : "l"(a), "l"(b));
}

// ---------------- per-launch reset (graph replays reuse device globals) ---
__global__ void reset_kernel() {
    if (threadIdx.x == 0) g_cnt = 0;
}

// ---------------- token dtype detection ----------------------------------
__global__ void detect_tok_kernel(const int* __restrict__ p) {
    __shared__ int bad;
    if (threadIdx.x == 0) bad = 0;
    __syncthreads();
    int mybad = 0;
    for (int i = threadIdx.x; i < SEQ / 2; i += blockDim.x) {
        int lo = p[2 * i];
        int hi = p[2 * i + 1];
        if (hi != 0 || lo < 0 || lo >= VOCAB) mybad = 1;
    }
    if (mybad) atomicOr(&bad, 1);
    __syncthreads();
    if (threadIdx.x == 0) g_tok64 = bad ? 0 : 1;
}

// ---------------- X = E @ W_e^T + b  (gathered GEMM, 128x128x16) ----------
#define BM 128
#define BN 128
#define BK 16
#define GTHREADS 256

__global__ void __launch_bounds__(GTHREADS, 1)
gemm_x_kernel(const int* __restrict__ toks,
              const float* __restrict__ emb,
              const float* __restrict__ Wi2h,
              const float* __restrict__ bias) {
    __shared__ __align__(16) float As[BK][BM + 4];
    __shared__ __align__(16) float Bs[BK][BN + 4];
    __shared__ int stok[BM];

    const int tid = threadIdx.x;
    const int t0 = blockIdx.y * BM;        // token (M) tile
    const int r0 = blockIdx.x * BN;        // hidden-row (N) tile
    const int tok64 = g_tok64;

    if (tid < BM) {
        int t = t0 + tid;
        stok[tid] = tok64 ? toks[2 * t] : toks[t];
    }
    __syncthreads();

    const int tx = tid & 15;   // N micro: cols r0 + tx*8 .. +7
    const int ty = tid >> 4;   // M micro: rows t0 + ty*8 .. +7

    float acc[8][8];
#pragma unroll
    for (int i = 0; i < 8; i++)
#pragma unroll
        for (int j = 0; j < 8; j++) acc[i][j] = 0.f;

    // loader mapping: v = tid + i*256 in [0,512): m = v>>2 (0..127), k4 = v&3
    for (int kk = 0; kk < EMB; kk += BK) {
#pragma unroll
        for (int i = 0; i < 2; i++) {
            int v = tid + i * GTHREADS;
            int m = v >> 2;
            int k = (v & 3) << 2;
            float4 a = *(const float4*)&emb[(size_t)stok[m] * EMB + kk + k];
            As[k + 0][m] = a.x; As[k + 1][m] = a.y;
            As[k + 2][m] = a.z; As[k + 3][m] = a.w;
            float4 b = *(const float4*)&Wi2h[(size_t)(r0 + m) * WSTRIDE + kk + k];
            Bs[k + 0][m] = b.x; Bs[k + 1][m] = b.y;
            Bs[k + 2][m] = b.z; Bs[k + 3][m] = b.w;
        }
        __syncthreads();
#pragma unroll
        for (int k = 0; k < BK; k++) {
            float a[8], b[8];
            *(float4*)&a[0] = *(const float4*)&As[k][ty * 8];
            *(float4*)&a[4] = *(const float4*)&As[k][ty * 8 + 4];
            *(float4*)&b[0] = *(const float4*)&Bs[k][tx * 8];
            *(float4*)&b[4] = *(const float4*)&Bs[k][tx * 8 + 4];
#pragma unroll
            for (int i = 0; i < 8; i++)
#pragma unroll
                for (int j = 0; j < 8; j++) acc[i][j] += a[i] * b[j];
        }
        __syncthreads();
    }

    float bv[8];
#pragma unroll
    for (int j = 0; j < 8; j++) bv[j] = bias[r0 + tx * 8 + j];

#pragma unroll
    for (int i = 0; i < 8; i++) {
        int t = t0 + ty * 8 + i;
        float o[8];
#pragma unroll
        for (int j = 0; j < 8; j++) o[j] = acc[i][j] + bv[j];
        *(float4*)&g_X[(size_t)t * HID + r0 + tx * 8]     = *(float4*)&o[0];
        *(float4*)&g_X[(size_t)t * HID + r0 + tx * 8 + 4] = *(float4*)&o[4];
    }
}

// ---------------- persistent recurrence kernel ----------------------------
#define ROWS_PER_CTA (HID / NCTA)  // 16
#define RTHREADS 512               // 16 warps

__global__ void __launch_bounds__(RTHREADS, 1)
rnn_kernel(const float* __restrict__ Wi2h,
           const float* __restrict__ Wh2o,
           const float* __restrict__ bh2o,
           float* __restrict__ out) {
    __shared__ __align__(16) float sh[HID];
    __shared__ float sred[64];

    const int tid = threadIdx.x;
    const int cta = blockIdx.x;
    const int r0  = cta * ROWS_PER_CTA;
    const int repl = cta & (NREP - 1);

    const int w = tid >> 5, l = tid & 31;
    const int grp = w & 3;   // rows r0 + 4*grp .. +3
    const int q   = w >> 2;  // h-slice [512q, 512(q+1))

    // ---- W_h slice into registers, packed f32x2: 4 rows x 8 u64 per lane --
    unsigned long long Wr[4][8];
#pragma unroll
    for (int rr = 0; rr < 4; rr++)
#pragma unroll
        for (int k = 0; k < 4; k++) {
            float4 wv = *(const float4*)&Wi2h[
                (size_t)(r0 + 4 * grp + rr) * WSTRIDE + EMB
                + (q << 9) + (l << 2) + (k << 7)];
            Wr[rr][2 * k]     = pack2(wv.x, wv.y);
            Wr[rr][2 * k + 1] = pack2(wv.z, wv.w);
        }

    for (int t = 0; t < SEQ; t++) {
        // prefetch this CTA's X[t] slice
        float xv = 0.f;
        if (tid < ROWS_PER_CTA) xv = __ldcg(&g_X[(size_t)t * HID + r0 + tid]);

        if (t > 0) {
            // warp 0 polls the arrival counter directly (>= 128*t)
            if (w == 0) {
                const unsigned tgt = (unsigned)t << 7;
                unsigned e;
                do { e = ld_relaxed(&g_cnt); }
                while (__any_sync(0xffffffffu, e < tgt));
                fence_acq();
            }
            __syncthreads();   // bar1: h_{t-1} complete & visible CTA-wide

            // stage distinct chunk w of h_{t-1} from this CTA's replica
            const float* hprev = g_hrep[(t - 1) & 1][repl];
            float4 ch = __ldcg((const float4*)&hprev[(w << 7) + (l << 2)]);
            *(float4*)&sh[(w << 7) + (l << 2)] = ch;
            __syncthreads();   // bar2: full h staged

            const float4* sh4 = (const float4*)sh;
            unsigned long long acc2[4];
#pragma unroll
            for (int rr = 0; rr < 4; rr++) acc2[rr] = pack2(0.f, 0.f);

#pragma unroll
            for (int k = 0; k < 4; k++) {
                float4 hv = sh4[(q << 7) + (k << 5) + l];
                unsigned long long h0 = pack2(hv.x, hv.y);
                unsigned long long h1 = pack2(hv.z, hv.w);
#pragma unroll
                for (int rr = 0; rr < 4; rr++) {
                    ffma2(acc2[rr], Wr[rr][2 * k],     h0);
                    ffma2(acc2[rr], Wr[rr][2 * k + 1], h1);
                }
            }

#pragma unroll
            for (int rr = 0; rr < 4; rr++) {
                float lo, hi;
                unpack2(lo, hi, acc2[rr]);
                float v = lo + hi;
                v += __shfl_xor_sync(0xffffffffu, v, 16);
                v += __shfl_xor_sync(0xffffffffu, v, 8);
                v += __shfl_xor_sync(0xffffffffu, v, 4);
                v += __shfl_xor_sync(0xffffffffu, v, 2);
                v += __shfl_xor_sync(0xffffffffu, v, 1);
                if (l == 0) sred[w * 4 + rr] = v;
            }
            __syncthreads();   // bar3: sred ready; orders ALL staging loads
                               //       before warp0's arrival below

            if (tid < ROWS_PER_CTA) {
                int g = tid >> 2, rr = tid & 3;
                float v = xv;
#pragma unroll
                for (int qq = 0; qq < 4; qq++)
                    v += sred[((qq << 2) | g) * 4 + rr];
#pragma unroll
                for (int r = 0; r < NREP; r++)
                    g_hrep[t & 1][r][r0 + tid] = v;
            }
        } else {
            // h after first token: W_h @ 0 + X[0] = X[0]
            if (tid < ROWS_PER_CTA) {
#pragma unroll
                for (int r = 0; r < NREP; r++)
                    g_hrep[0][r][r0 + tid] = xv;
            }
        }

        // arrive: h stores (lanes 0..15 of warp 0) -> syncwarp -> counter
        if (w == 0) {
            __syncwarp();
            if (l == 0) red_add_release(&g_cnt, 1u);
        }
    }

    // readout: out = sigmoid(W_h2o @ h_final + b_h2o)
    if (cta == 0) {
        if (w == 0) {
            const unsigned tgt = (unsigned)SEQ << 7;
            unsigned e;
            do { e = ld_relaxed(&g_cnt); }
            while (__any_sync(0xffffffffu, e < tgt));
            fence_acq();
        }
        __syncthreads();
        const float* hf = g_hrep[(SEQ - 1) & 1][0];
        float s = 0.f;
        for (int j = tid; j < HID; j += RTHREADS) s += __ldcg(&hf[j]) * Wh2o[j];
#pragma unroll
        for (int o = 16; o > 0; o >>= 1) s += __shfl_xor_sync(0xffffffffu, s, o);
        __syncthreads();
        if (l == 0) sred[w] = s;
        __syncthreads();
        if (tid == 0) {
            float tot = 0.f;
#pragma unroll
            for (int i = 0; i < RTHREADS / 32; i++) tot += sred[i];
            tot += bh2o[0];
            out[0] = 1.f / (1.f + expf(-tot));
        }
    }
}

// ---------------- launch ---------------------------------------------------
extern "C" void kernel_launch(void* const* d_in, const int* in_sizes, int n_in,
                              void* d_out, int out_size) {
    const int*   toks = (const int*)d_in[0];
    const float* emb  = (const float*)d_in[1];
    const float* Wi2h = (const float*)d_in[2];
    const float* bi2h = (const float*)d_in[3];
    const float* Wh2o = (const float*)d_in[4];
    const float* bh2o = (const float*)d_in[5];
    float* out = (float*)d_out;

    reset_kernel<<<1, 32>>>();
    detect_tok_kernel<<<1, 256>>>(toks);
    gemm_x_kernel<<<dim3(HID / BN, SEQ / BM), GTHREADS>>>(toks, emb, Wi2h, bi2h);
    rnn_kernel<<<NCTA, RTHREADS>>>(Wi2h, Wh2o, bh2o, out);
}

// round 8
// speedup vs baseline: 4.8080x; 1.5383x over previous
#include <cuda_runtime.h>
#include <math.h>

#define SEQ   2048
#define SEQ2  (SEQ / 2)       // 1024 blocked steps
#define EMB   1024
#define HID   2048
#define VOCAB 50257
#define WSTRIDE (EMB + HID)   // 3072, row stride of W_i2h

#define NCTA 128
#define NREP 4

// ---------------- scratch (device globals: allocation-free rule) ----------
__device__ __align__(16) float g_X [SEQ  * HID];      // 16 MB: per-token input
__device__ __align__(16) float g_X2[SEQ2 * HID];      //  8 MB: blocked input
__device__ __align__(16) float g_W2[HID * HID];       // 16 MB: W_h^2
__device__ __align__(16) float g_hrep[2][NREP][HID];  // replicated h, dbl-buffered
__device__ unsigned g_cnt;                            // monotonic arrival counter
__device__ int g_tok64 = 0;

// ---------------- memory-order / packed-math helpers ----------------------
__device__ __forceinline__ unsigned ld_relaxed(const unsigned* p) {
    unsigned v;
    asm volatile("ld.relaxed.gpu.global.u32 %0, [%1];" : "=r"(v) : "l"(p) : "memory");
    return v;
}
__device__ __forceinline__ void red_add_release(unsigned* p, unsigned v) {
    asm volatile("red.release.gpu.global.add.u32 [%0], %1;" :: "l"(p), "r"(v) : "memory");
}
__device__ __forceinline__ void fence_acq() {
    asm volatile("fence.acq_rel.gpu;" ::: "memory");
}
__device__ __forceinline__ unsigned long long pack2(float lo, float hi) {
    unsigned long long r;
    asm("mov.b64 %0, {%1, %2};" : "=l"(r) : "f"(lo), "f"(hi));
    return r;
}
__device__ __forceinline__ void unpack2(float& lo, float& hi, unsigned long long v) {
    asm("mov.b64 {%0, %1}, %2;" : "=f"(lo), "=f"(hi) : "l"(v));
}
__device__ __forceinline__ void ffma2(unsigned long long& acc,
                                      unsigned long long a, unsigned long long b) {
    asm("fma.rn.f32x2 %0, %1, %2, %0;" : "+l"(acc) : "l"(a), "l"(b));
}

// ---------------- per-launch reset ----------------------------------------
__global__ void reset_kernel() {
    if (threadIdx.x == 0) g_cnt = 0;
}

// ---------------- token dtype detection -----------------------------------
__global__ void detect_tok_kernel(const int* __restrict__ p) {
    __shared__ int bad;
    if (threadIdx.x == 0) bad = 0;
    __syncthreads();
    int mybad = 0;
    for (int i = threadIdx.x; i < SEQ / 2; i += blockDim.x) {
        int lo = p[2 * i];
        int hi = p[2 * i + 1];
        if (hi != 0 || lo < 0 || lo >= VOCAB) mybad = 1;
    }
    if (mybad) atomicOr(&bad, 1);
    __syncthreads();
    if (threadIdx.x == 0) g_tok64 = bad ? 0 : 1;
}

// =================== GEMM tiles: 128x128x16, 256 thr, 8x8 micro ==========
#define BM 128
#define BN 128
#define BK 16
#define GTHREADS 256

// ---------------- X = E @ W_e^T + b ---------------------------------------
__global__ void __launch_bounds__(GTHREADS, 1)
gemm_x_kernel(const int* __restrict__ toks,
              const float* __restrict__ emb,
              const float* __restrict__ Wi2h,
              const float* __restrict__ bias) {
    __shared__ __align__(16) float As[BK][BM + 4];
    __shared__ __align__(16) float Bs[BK][BN + 4];
    __shared__ int stok[BM];

    const int tid = threadIdx.x;
    const int t0 = blockIdx.y * BM;        // token tile
    const int r0 = blockIdx.x * BN;        // hidden-row tile
    const int tok64 = g_tok64;

    if (tid < BM) {
        int t = t0 + tid;
        stok[tid] = tok64 ? toks[2 * t] : toks[t];
    }
    __syncthreads();

    const int tx = tid & 15;
    const int ty = tid >> 4;

    float acc[8][8];
#pragma unroll
    for (int i = 0; i < 8; i++)
#pragma unroll
        for (int j = 0; j < 8; j++) acc[i][j] = 0.f;

    for (int kk = 0; kk < EMB; kk += BK) {
#pragma unroll
        for (int i = 0; i < 2; i++) {
            int v = tid + i * GTHREADS;
            int m = v >> 2;
            int k = (v & 3) << 2;
            float4 a = *(const float4*)&emb[(size_t)stok[m] * EMB + kk + k];
            As[k + 0][m] = a.x; As[k + 1][m] = a.y;
            As[k + 2][m] = a.z; As[k + 3][m] = a.w;
            float4 b = *(const float4*)&Wi2h[(size_t)(r0 + m) * WSTRIDE + kk + k];
            Bs[k + 0][m] = b.x; Bs[k + 1][m] = b.y;
            Bs[k + 2][m] = b.z; Bs[k + 3][m] = b.w;
        }
        __syncthreads();
#pragma unroll
        for (int k = 0; k < BK; k++) {
            float a[8], b[8];
            *(float4*)&a[0] = *(const float4*)&As[k][ty * 8];
            *(float4*)&a[4] = *(const float4*)&As[k][ty * 8 + 4];
            *(float4*)&b[0] = *(const float4*)&Bs[k][tx * 8];
            *(float4*)&b[4] = *(const float4*)&Bs[k][tx * 8 + 4];
#pragma unroll
            for (int i = 0; i < 8; i++)
#pragma unroll
                for (int j = 0; j < 8; j++) acc[i][j] += a[i] * b[j];
        }
        __syncthreads();
    }

    float bv[8];
#pragma unroll
    for (int j = 0; j < 8; j++) bv[j] = bias[r0 + tx * 8 + j];

#pragma unroll
    for (int i = 0; i < 8; i++) {
        int t = t0 + ty * 8 + i;
        float o[8];
#pragma unroll
        for (int j = 0; j < 8; j++) o[j] = acc[i][j] + bv[j];
        *(float4*)&g_X[(size_t)t * HID + r0 + tx * 8]     = *(float4*)&o[0];
        *(float4*)&g_X[(size_t)t * HID + r0 + tx * 8 + 4] = *(float4*)&o[4];
    }
}

// ---------------- W2 = W_h @ W_h  (C[i][j] = sum_k Wh[i][k] Wh[k][j]) ------
__global__ void __launch_bounds__(GTHREADS, 1)
gemm_w2_kernel(const float* __restrict__ Wi2h) {
    __shared__ __align__(16) float As[BK][BM + 4];
    __shared__ __align__(16) float Bs[BK][BN + 4];

    const int tid = threadIdx.x;
    const int i0 = blockIdx.y * BM;
    const int j0 = blockIdx.x * BN;

    const int tx = tid & 15;
    const int ty = tid >> 4;

    float acc[8][8];
#pragma unroll
    for (int i = 0; i < 8; i++)
#pragma unroll
        for (int j = 0; j < 8; j++) acc[i][j] = 0.f;

    for (int kk = 0; kk < HID; kk += BK) {
        // A tile: Wh[i0+m][kk+k] (row-major, K contiguous)
#pragma unroll
        for (int i = 0; i < 2; i++) {
            int v = tid + i * GTHREADS;
            int m = v >> 2;
            int k = (v & 3) << 2;
            float4 a = *(const float4*)&Wi2h[(size_t)(i0 + m) * WSTRIDE + EMB + kk + k];
            As[k + 0][m] = a.x; As[k + 1][m] = a.y;
            As[k + 2][m] = a.z; As[k + 3][m] = a.w;
        }
        // B tile: Wh[kk+k][j0+j] (16 rows x 128 contiguous cols)
#pragma unroll
        for (int i = 0; i < 2; i++) {
            int v = tid + i * GTHREADS;
            int k = v >> 5;              // 0..15
            int j = (v & 31) << 2;       // 0..124
            float4 b = *(const float4*)&Wi2h[(size_t)(kk + k) * WSTRIDE + EMB + j0 + j];
            *(float4*)&Bs[k][j] = b;
        }
        __syncthreads();
#pragma unroll
        for (int k = 0; k < BK; k++) {
            float a[8], b[8];
            *(float4*)&a[0] = *(const float4*)&As[k][ty * 8];
            *(float4*)&a[4] = *(const float4*)&As[k][ty * 8 + 4];
            *(float4*)&b[0] = *(const float4*)&Bs[k][tx * 8];
            *(float4*)&b[4] = *(const float4*)&Bs[k][tx * 8 + 4];
#pragma unroll
            for (int i = 0; i < 8; i++)
#pragma unroll
                for (int j = 0; j < 8; j++) acc[i][j] += a[i] * b[j];
        }
        __syncthreads();
    }

#pragma unroll
    for (int i = 0; i < 8; i++) {
        int r = i0 + ty * 8 + i;
        *(float4*)&g_W2[(size_t)r * HID + j0 + tx * 8]     = *(float4*)&acc[i][0];
        *(float4*)&g_W2[(size_t)r * HID + j0 + tx * 8 + 4] = *(float4*)&acc[i][4];
    }
}

// ---------------- X2[s] = W_h @ X[2s] + X[2s+1] ----------------------------
__global__ void __launch_bounds__(GTHREADS, 1)
gemm_x2_kernel(const float* __restrict__ Wi2h) {
    __shared__ __align__(16) float As[BK][BM + 4];
    __shared__ __align__(16) float Bs[BK][BN + 4];

    const int tid = threadIdx.x;
    const int s0 = blockIdx.y * BM;        // blocked-step tile
    const int r0 = blockIdx.x * BN;        // hidden-row tile

    const int tx = tid & 15;
    const int ty = tid >> 4;

    float acc[8][8];
#pragma unroll
    for (int i = 0; i < 8; i++)
#pragma unroll
        for (int j = 0; j < 8; j++) acc[i][j] = 0.f;

    for (int kk = 0; kk < HID; kk += BK) {
#pragma unroll
        for (int i = 0; i < 2; i++) {
            int v = tid + i * GTHREADS;
            int m = v >> 2;
            int k = (v & 3) << 2;
            // A[s][k] = X[2s][k]
            float4 a = *(const float4*)&g_X[(size_t)(2 * (s0 + m)) * HID + kk + k];
            As[k + 0][m] = a.x; As[k + 1][m] = a.y;
            As[k + 2][m] = a.z; As[k + 3][m] = a.w;
            // B[i][k] = Wh[r0+m][kk+k]
            float4 b = *(const float4*)&Wi2h[(size_t)(r0 + m) * WSTRIDE + EMB + kk + k];
            Bs[k + 0][m] = b.x; Bs[k + 1][m] = b.y;
            Bs[k + 2][m] = b.z; Bs[k + 3][m] = b.w;
        }
        __syncthreads();
#pragma unroll
        for (int k = 0; k < BK; k++) {
            float a[8], b[8];
            *(float4*)&a[0] = *(const float4*)&As[k][ty * 8];
            *(float4*)&a[4] = *(const float4*)&As[k][ty * 8 + 4];
            *(float4*)&b[0] = *(const float4*)&Bs[k][tx * 8];
            *(float4*)&b[4] = *(const float4*)&Bs[k][tx * 8 + 4];
#pragma unroll
            for (int i = 0; i < 8; i++)
#pragma unroll
                for (int j = 0; j < 8; j++) acc[i][j] += a[i] * b[j];
        }
        __syncthreads();
    }

#pragma unroll
    for (int i = 0; i < 8; i++) {
        int s = s0 + ty * 8 + i;
        float4 e0 = *(const float4*)&g_X[(size_t)(2 * s + 1) * HID + r0 + tx * 8];
        float4 e1 = *(const float4*)&g_X[(size_t)(2 * s + 1) * HID + r0 + tx * 8 + 4];
        float o[8];
        o[0] = acc[i][0] + e0.x; o[1] = acc[i][1] + e0.y;
        o[2] = acc[i][2] + e0.z; o[3] = acc[i][3] + e0.w;
        o[4] = acc[i][4] + e1.x; o[5] = acc[i][5] + e1.y;
        o[6] = acc[i][6] + e1.z; o[7] = acc[i][7] + e1.w;
        *(float4*)&g_X2[(size_t)s * HID + r0 + tx * 8]     = *(float4*)&o[0];
        *(float4*)&g_X2[(size_t)s * HID + r0 + tx * 8 + 4] = *(float4*)&o[4];
    }
}

// ---------------- persistent recurrence kernel (1024 steps, W2/X2) --------
#define ROWS_PER_CTA (HID / NCTA)  // 16
#define RTHREADS 512               // 16 warps

__global__ void __launch_bounds__(RTHREADS, 1)
rnn_kernel(const float* __restrict__ Wh2o,
           const float* __restrict__ bh2o,
           float* __restrict__ out) {
    __shared__ __align__(16) float sh[HID];
    __shared__ float sred[64];

    const int tid = threadIdx.x;
    const int cta = blockIdx.x;
    const int r0  = cta * ROWS_PER_CTA;
    const int repl = cta & (NREP - 1);

    const int w = tid >> 5, l = tid & 31;
    const int grp = w & 3;   // rows r0 + 4*grp .. +3
    const int q   = w >> 2;  // h-slice [512q, 512(q+1))

    // ---- W2 slice into registers, packed f32x2: 4 rows x 8 u64 per lane ---
    unsigned long long Wr[4][8];
#pragma unroll
    for (int rr = 0; rr < 4; rr++)
#pragma unroll
        for (int k = 0; k < 4; k++) {
            float4 wv = *(const float4*)&g_W2[
                (size_t)(r0 + 4 * grp + rr) * HID
                + (q << 9) + (l << 2) + (k << 7)];
            Wr[rr][2 * k]     = pack2(wv.x, wv.y);
            Wr[rr][2 * k + 1] = pack2(wv.z, wv.w);
        }

    for (int t = 0; t < SEQ2; t++) {
        // prefetch this CTA's X2[t] slice
        float xv = 0.f;
        if (tid < ROWS_PER_CTA) xv = __ldcg(&g_X2[(size_t)t * HID + r0 + tid]);

        if (t > 0) {
            // warp 0 polls the arrival counter directly (>= 128*t)
            if (w == 0) {
                const unsigned tgt = (unsigned)t << 7;
                unsigned e;
                do { e = ld_relaxed(&g_cnt); }
                while (__any_sync(0xffffffffu, e < tgt));
                fence_acq();
            }
            __syncthreads();   // bar1: h_{t-1} complete & visible CTA-wide

            // stage distinct chunk w of h_{t-1} from this CTA's replica
            const float* hprev = g_hrep[(t - 1) & 1][repl];
            float4 ch = __ldcg((const float4*)&hprev[(w << 7) + (l << 2)]);
            *(float4*)&sh[(w << 7) + (l << 2)] = ch;
            __syncthreads();   // bar2: full h staged

            const float4* sh4 = (const float4*)sh;
            unsigned long long acc2[4];
#pragma unroll
            for (int rr = 0; rr < 4; rr++) acc2[rr] = pack2(0.f, 0.f);

#pragma unroll
            for (int k = 0; k < 4; k++) {
                float4 hv = sh4[(q << 7) + (k << 5) + l];
                unsigned long long h0 = pack2(hv.x, hv.y);
                unsigned long long h1 = pack2(hv.z, hv.w);
#pragma unroll
                for (int rr = 0; rr < 4; rr++) {
                    ffma2(acc2[rr], Wr[rr][2 * k],     h0);
                    ffma2(acc2[rr], Wr[rr][2 * k + 1], h1);
                }
            }

#pragma unroll
            for (int rr = 0; rr < 4; rr++) {
                float lo, hi;
                unpack2(lo, hi, acc2[rr]);
                float v = lo + hi;
                v += __shfl_xor_sync(0xffffffffu, v, 16);
                v += __shfl_xor_sync(0xffffffffu, v, 8);
                v += __shfl_xor_sync(0xffffffffu, v, 4);
                v += __shfl_xor_sync(0xffffffffu, v, 2);
                v += __shfl_xor_sync(0xffffffffu, v, 1);
                if (l == 0) sred[w * 4 + rr] = v;
            }
            __syncthreads();   // bar3: sred ready; orders staging loads before arrival

            if (tid < ROWS_PER_CTA) {
                int g = tid >> 2, rr = tid & 3;
                float v = xv;
#pragma unroll
                for (int qq = 0; qq < 4; qq++)
                    v += sred[((qq << 2) | g) * 4 + rr];
#pragma unroll
                for (int r = 0; r < NREP; r++)
                    g_hrep[t & 1][r][r0 + tid] = v;
            }
        } else {
            // first blocked step: h_2 = W2 @ 0 + X2[0] = X2[0]
            if (tid < ROWS_PER_CTA) {
#pragma unroll
                for (int r = 0; r < NREP; r++)
                    g_hrep[0][r][r0 + tid] = xv;
            }
        }

        // arrive
        if (w == 0) {
            __syncwarp();
            if (l == 0) red_add_release(&g_cnt, 1u);
        }
    }

    // readout: out = sigmoid(W_h2o @ h_final + b_h2o)
    if (cta == 0) {
        if (w == 0) {
            const unsigned tgt = (unsigned)SEQ2 << 7;
            unsigned e;
            do { e = ld_relaxed(&g_cnt); }
            while (__any_sync(0xffffffffu, e < tgt));
            fence_acq();
        }
        __syncthreads();
        const float* hf = g_hrep[(SEQ2 - 1) & 1][0];
        float s = 0.f;
        for (int j = tid; j < HID; j += RTHREADS) s += __ldcg(&hf[j]) * Wh2o[j];
#pragma unroll
        for (int o = 16; o > 0; o >>= 1) s += __shfl_xor_sync(0xffffffffu, s, o);
        __syncthreads();
        if (l == 0) sred[w] = s;
        __syncthreads();
        if (tid == 0) {
            float tot = 0.f;
#pragma unroll
            for (int i = 0; i < RTHREADS / 32; i++) tot += sred[i];
            tot += bh2o[0];
            out[0] = 1.f / (1.f + expf(-tot));
        }
    }
}

// ---------------- launch ---------------------------------------------------
extern "C" void kernel_launch(void* const* d_in, const int* in_sizes, int n_in,
                              void* d_out, int out_size) {
    const int*   toks = (const int*)d_in[0];
    const float* emb  = (const float*)d_in[1];
    const float* Wi2h = (const float*)d_in[2];
    const float* bi2h = (const float*)d_in[3];
    const float* Wh2o = (const float*)d_in[4];
    const float* bh2o = (const float*)d_in[5];
    float* out = (float*)d_out;

    reset_kernel<<<1, 32>>>();
    detect_tok_kernel<<<1, 256>>>(toks);
    gemm_x_kernel <<<dim3(HID / BN, SEQ  / BM), GTHREADS>>>(toks, emb, Wi2h, bi2h);
    gemm_w2_kernel<<<dim3(HID / BN, HID  / BM), GTHREADS>>>(Wi2h);
    gemm_x2_kernel<<<dim3(HID / BN, SEQ2 / BM), GTHREADS>>>(Wi2h);
    rnn_kernel<<<NCTA, RTHREADS>>>(Wh2o, bh2o, out);
}

// round 9
// speedup vs baseline: 5.9031x; 1.2278x over previous
#include <cuda_runtime.h>
#include <math.h>

#define SEQ   2048
#define SEQ2  (SEQ / 2)       // 1024 blocked-2 steps
#define SEQ4  (SEQ / 4)       // 512 blocked-4 steps
#define EMB   1024
#define HID   2048
#define VOCAB 50257
#define WSTRIDE (EMB + HID)   // 3072, row stride of W_i2h

#define NCTA 128
#define NREP 4

// ---------------- scratch (device globals: allocation-free rule) ----------
__device__ __align__(16) float g_X [SEQ  * HID];      // 16 MB
__device__ __align__(16) float g_X2[SEQ2 * HID];      //  8 MB
__device__ __align__(16) float g_X4[SEQ4 * HID];      //  4 MB
__device__ __align__(16) float g_W2[HID * HID];       // 16 MB: W_h^2
__device__ __align__(16) float g_W4[HID * HID];       // 16 MB: W_h^4
__device__ __align__(16) float g_hrep[2][NREP][HID];  // replicated h, dbl-buffered
__device__ unsigned g_cnt;                            // monotonic arrival counter
__device__ int g_tok64 = 0;

// ---------------- memory-order / packed-math helpers ----------------------
__device__ __forceinline__ unsigned ld_relaxed(const unsigned* p) {
    unsigned v;
    asm volatile("ld.relaxed.gpu.global.u32 %0, [%1];" : "=r"(v) : "l"(p) : "memory");
    return v;
}
__device__ __forceinline__ void red_add_release(unsigned* p, unsigned v) {
    asm volatile("red.release.gpu.global.add.u32 [%0], %1;" :: "l"(p), "r"(v) : "memory");
}
__device__ __forceinline__ void fence_acq() {
    asm volatile("fence.acq_rel.gpu;" ::: "memory");
}
__device__ __forceinline__ unsigned long long pack2(float lo, float hi) {
    unsigned long long r;
    asm("mov.b64 %0, {%1, %2};" : "=l"(r) : "f"(lo), "f"(hi));
    return r;
}
__device__ __forceinline__ void unpack2(float& lo, float& hi, unsigned long long v) {
    asm("mov.b64 {%0, %1}, %2;" : "=f"(lo), "=f"(hi) : "l"(v));
}
__device__ __forceinline__ void ffma2(unsigned long long& acc,
                                      unsigned long long a, unsigned long long b) {
    asm("fma.rn.f32x2 %0, %1, %2, %0;" : "+l"(acc) : "l"(a), "l"(b));
}

// ---------------- per-launch reset ----------------------------------------
__global__ void reset_kernel() {
    if (threadIdx.x == 0) g_cnt = 0;
}

// ---------------- token dtype detection -----------------------------------
__global__ void detect_tok_kernel(const int* __restrict__ p) {
    __shared__ int bad;
    if (threadIdx.x == 0) bad = 0;
    __syncthreads();
    int mybad = 0;
    for (int i = threadIdx.x; i < SEQ / 2; i += blockDim.x) {
        int lo = p[2 * i];
        int hi = p[2 * i + 1];
        if (hi != 0 || lo < 0 || lo >= VOCAB) mybad = 1;
    }
    if (mybad) atomicOr(&bad, 1);
    __syncthreads();
    if (threadIdx.x == 0) g_tok64 = bad ? 0 : 1;
}

// =================== GEMM tiles: 128x128x16, 256 thr, 8x8 micro ==========
#define BM 128
#define BN 128
#define BK 16
#define GTHREADS 256

// ---------------- X = E @ W_e^T + b ---------------------------------------
__global__ void __launch_bounds__(GTHREADS, 1)
gemm_x_kernel(const int* __restrict__ toks,
              const float* __restrict__ emb,
              const float* __restrict__ Wi2h,
              const float* __restrict__ bias) {
    __shared__ __align__(16) float As[BK][BM + 4];
    __shared__ __align__(16) float Bs[BK][BN + 4];
    __shared__ int stok[BM];

    const int tid = threadIdx.x;
    const int t0 = blockIdx.y * BM;
    const int r0 = blockIdx.x * BN;
    const int tok64 = g_tok64;

    if (tid < BM) {
        int t = t0 + tid;
        stok[tid] = tok64 ? toks[2 * t] : toks[t];
    }
    __syncthreads();

    const int tx = tid & 15;
    const int ty = tid >> 4;

    float acc[8][8];
#pragma unroll
    for (int i = 0; i < 8; i++)
#pragma unroll
        for (int j = 0; j < 8; j++) acc[i][j] = 0.f;

    for (int kk = 0; kk < EMB; kk += BK) {
#pragma unroll
        for (int i = 0; i < 2; i++) {
            int v = tid + i * GTHREADS;
            int m = v >> 2;
            int k = (v & 3) << 2;
            float4 a = *(const float4*)&emb[(size_t)stok[m] * EMB + kk + k];
            As[k + 0][m] = a.x; As[k + 1][m] = a.y;
            As[k + 2][m] = a.z; As[k + 3][m] = a.w;
            float4 b = *(const float4*)&Wi2h[(size_t)(r0 + m) * WSTRIDE + kk + k];
            Bs[k + 0][m] = b.x; Bs[k + 1][m] = b.y;
            Bs[k + 2][m] = b.z; Bs[k + 3][m] = b.w;
        }
        __syncthreads();
#pragma unroll
        for (int k = 0; k < BK; k++) {
            float a[8], b[8];
            *(float4*)&a[0] = *(const float4*)&As[k][ty * 8];
            *(float4*)&a[4] = *(const float4*)&As[k][ty * 8 + 4];
            *(float4*)&b[0] = *(const float4*)&Bs[k][tx * 8];
            *(float4*)&b[4] = *(const float4*)&Bs[k][tx * 8 + 4];
#pragma unroll
            for (int i = 0; i < 8; i++)
#pragma unroll
                for (int j = 0; j < 8; j++) acc[i][j] += a[i] * b[j];
        }
        __syncthreads();
    }

    float bv[8];
#pragma unroll
    for (int j = 0; j < 8; j++) bv[j] = bias[r0 + tx * 8 + j];

#pragma unroll
    for (int i = 0; i < 8; i++) {
        int t = t0 + ty * 8 + i;
        float o[8];
#pragma unroll
        for (int j = 0; j < 8; j++) o[j] = acc[i][j] + bv[j];
        *(float4*)&g_X[(size_t)t * HID + r0 + tx * 8]     = *(float4*)&o[0];
        *(float4*)&g_X[(size_t)t * HID + r0 + tx * 8 + 4] = *(float4*)&o[4];
    }
}

// ---------------- generic square product: C = A @ A2 (both HIDxHID views) --
// Used for W2 = Wh@Wh (strideA=WSTRIDE, offset EMB) and W4 = W2@W2.
template <int ASTRIDE, int AOFF>
__global__ void __launch_bounds__(GTHREADS, 1)
gemm_sq_kernel(const float* __restrict__ A, float* __restrict__ C) {
    __shared__ __align__(16) float As[BK][BM + 4];
    __shared__ __align__(16) float Bs[BK][BN + 4];

    const int tid = threadIdx.x;
    const int i0 = blockIdx.y * BM;
    const int j0 = blockIdx.x * BN;

    const int tx = tid & 15;
    const int ty = tid >> 4;

    float acc[8][8];
#pragma unroll
    for (int i = 0; i < 8; i++)
#pragma unroll
        for (int j = 0; j < 8; j++) acc[i][j] = 0.f;

    for (int kk = 0; kk < HID; kk += BK) {
        // A tile: A[i0+m][kk+k]
#pragma unroll
        for (int i = 0; i < 2; i++) {
            int v = tid + i * GTHREADS;
            int m = v >> 2;
            int k = (v & 3) << 2;
            float4 a = *(const float4*)&A[(size_t)(i0 + m) * ASTRIDE + AOFF + kk + k];
            As[k + 0][m] = a.x; As[k + 1][m] = a.y;
            As[k + 2][m] = a.z; As[k + 3][m] = a.w;
        }
        // B tile: A[kk+k][j0+j]
#pragma unroll
        for (int i = 0; i < 2; i++) {
            int v = tid + i * GTHREADS;
            int k = v >> 5;
            int j = (v & 31) << 2;
            float4 b = *(const float4*)&A[(size_t)(kk + k) * ASTRIDE + AOFF + j0 + j];
            *(float4*)&Bs[k][j] = b;
        }
        __syncthreads();
#pragma unroll
        for (int k = 0; k < BK; k++) {
            float a[8], b[8];
            *(float4*)&a[0] = *(const float4*)&As[k][ty * 8];
            *(float4*)&a[4] = *(const float4*)&As[k][ty * 8 + 4];
            *(float4*)&b[0] = *(const float4*)&Bs[k][tx * 8];
            *(float4*)&b[4] = *(const float4*)&Bs[k][tx * 8 + 4];
#pragma unroll
            for (int i = 0; i < 8; i++)
#pragma unroll
                for (int j = 0; j < 8; j++) acc[i][j] += a[i] * b[j];
        }
        __syncthreads();
    }

#pragma unroll
    for (int i = 0; i < 8; i++) {
        int r = i0 + ty * 8 + i;
        *(float4*)&C[(size_t)r * HID + j0 + tx * 8]     = *(float4*)&acc[i][0];
        *(float4*)&C[(size_t)r * HID + j0 + tx * 8 + 4] = *(float4*)&acc[i][4];
    }
}

// ---------------- fold: Y[s] = W @ Xin[2s] + Xin[2s+1] ---------------------
// W is an HID x HID row-major matrix view (stride WSTRIDE_/off) .
template <int WSTRIDE_, int WOFF>
__global__ void __launch_bounds__(GTHREADS, 1)
gemm_fold_kernel(const float* __restrict__ W,
                 const float* __restrict__ Xin,
                 float* __restrict__ Y) {
    __shared__ __align__(16) float As[BK][BM + 4];
    __shared__ __align__(16) float Bs[BK][BN + 4];

    const int tid = threadIdx.x;
    const int s0 = blockIdx.y * BM;        // blocked-step tile
    const int r0 = blockIdx.x * BN;        // hidden-row tile

    const int tx = tid & 15;
    const int ty = tid >> 4;

    float acc[8][8];
#pragma unroll
    for (int i = 0; i < 8; i++)
#pragma unroll
        for (int j = 0; j < 8; j++) acc[i][j] = 0.f;

    for (int kk = 0; kk < HID; kk += BK) {
#pragma unroll
        for (int i = 0; i < 2; i++) {
            int v = tid + i * GTHREADS;
            int m = v >> 2;
            int k = (v & 3) << 2;
            // A[s][k] = Xin[2s][k]
            float4 a = *(const float4*)&Xin[(size_t)(2 * (s0 + m)) * HID + kk + k];
            As[k + 0][m] = a.x; As[k + 1][m] = a.y;
            As[k + 2][m] = a.z; As[k + 3][m] = a.w;
            // B[j][k] = W[r0+m][kk+k]
            float4 b = *(const float4*)&W[(size_t)(r0 + m) * WSTRIDE_ + WOFF + kk + k];
            Bs[k + 0][m] = b.x; Bs[k + 1][m] = b.y;
            Bs[k + 2][m] = b.z; Bs[k + 3][m] = b.w;
        }
        __syncthreads();
#pragma unroll
        for (int k = 0; k < BK; k++) {
            float a[8], b[8];
            *(float4*)&a[0] = *(const float4*)&As[k][ty * 8];
            *(float4*)&a[4] = *(const float4*)&As[k][ty * 8 + 4];
            *(float4*)&b[0] = *(const float4*)&Bs[k][tx * 8];
            *(float4*)&b[4] = *(const float4*)&Bs[k][tx * 8 + 4];
#pragma unroll
            for (int i = 0; i < 8; i++)
#pragma unroll
                for (int j = 0; j < 8; j++) acc[i][j] += a[i] * b[j];
        }
        __syncthreads();
    }

#pragma unroll
    for (int i = 0; i < 8; i++) {
        int s = s0 + ty * 8 + i;
        float4 e0 = *(const float4*)&Xin[(size_t)(2 * s + 1) * HID + r0 + tx * 8];
        float4 e1 = *(const float4*)&Xin[(size_t)(2 * s + 1) * HID + r0 + tx * 8 + 4];
        float o[8];
        o[0] = acc[i][0] + e0.x; o[1] = acc[i][1] + e0.y;
        o[2] = acc[i][2] + e0.z; o[3] = acc[i][3] + e0.w;
        o[4] = acc[i][4] + e1.x; o[5] = acc[i][5] + e1.y;
        o[6] = acc[i][6] + e1.z; o[7] = acc[i][7] + e1.w;
        *(float4*)&Y[(size_t)s * HID + r0 + tx * 8]     = *(float4*)&o[0];
        *(float4*)&Y[(size_t)s * HID + r0 + tx * 8 + 4] = *(float4*)&o[4];
    }
}

// ---------------- persistent recurrence kernel (512 steps, W4/X4) ---------
#define ROWS_PER_CTA (HID / NCTA)  // 16
#define RTHREADS 512               // 16 warps

__global__ void __launch_bounds__(RTHREADS, 1)
rnn_kernel(const float* __restrict__ Wh2o,
           const float* __restrict__ bh2o,
           float* __restrict__ out) {
    __shared__ __align__(16) float sh[HID];
    __shared__ float sred[64];

    const int tid = threadIdx.x;
    const int cta = blockIdx.x;
    const int r0  = cta * ROWS_PER_CTA;
    const int repl = cta & (NREP - 1);

    const int w = tid >> 5, l = tid & 31;
    const int grp = w & 3;   // rows r0 + 4*grp .. +3
    const int q   = w >> 2;  // h-slice [512q, 512(q+1))

    // ---- W4 slice into registers, packed f32x2 ----------------------------
    unsigned long long Wr[4][8];
#pragma unroll
    for (int rr = 0; rr < 4; rr++)
#pragma unroll
        for (int k = 0; k < 4; k++) {
            float4 wv = *(const float4*)&g_W4[
                (size_t)(r0 + 4 * grp + rr) * HID
                + (q << 9) + (l << 2) + (k << 7)];
            Wr[rr][2 * k]     = pack2(wv.x, wv.y);
            Wr[rr][2 * k + 1] = pack2(wv.z, wv.w);
        }

    for (int t = 0; t < SEQ4; t++) {
        // prefetch this CTA's X4[t] slice
        float xv = 0.f;
        if (tid < ROWS_PER_CTA) xv = __ldcg(&g_X4[(size_t)t * HID + r0 + tid]);

        if (t > 0) {
            if (w == 0) {
                const unsigned tgt = (unsigned)t << 7;
                unsigned e;
                do { e = ld_relaxed(&g_cnt); }
                while (__any_sync(0xffffffffu, e < tgt));
                fence_acq();
            }
            __syncthreads();   // bar1

            const float* hprev = g_hrep[(t - 1) & 1][repl];
            float4 ch = __ldcg((const float4*)&hprev[(w << 7) + (l << 2)]);
            *(float4*)&sh[(w << 7) + (l << 2)] = ch;
            __syncthreads();   // bar2

            const float4* sh4 = (const float4*)sh;
            unsigned long long acc2[4];
#pragma unroll
            for (int rr = 0; rr < 4; rr++) acc2[rr] = pack2(0.f, 0.f);

#pragma unroll
            for (int k = 0; k < 4; k++) {
                float4 hv = sh4[(q << 7) + (k << 5) + l];
                unsigned long long h0 = pack2(hv.x, hv.y);
                unsigned long long h1 = pack2(hv.z, hv.w);
#pragma unroll
                for (int rr = 0; rr < 4; rr++) {
                    ffma2(acc2[rr], Wr[rr][2 * k],     h0);
                    ffma2(acc2[rr], Wr[rr][2 * k + 1], h1);
                }
            }

#pragma unroll
            for (int rr = 0; rr < 4; rr++) {
                float lo, hi;
                unpack2(lo, hi, acc2[rr]);
                float v = lo + hi;
                v += __shfl_xor_sync(0xffffffffu, v, 16);
                v += __shfl_xor_sync(0xffffffffu, v, 8);
                v += __shfl_xor_sync(0xffffffffu, v, 4);
                v += __shfl_xor_sync(0xffffffffu, v, 2);
                v += __shfl_xor_sync(0xffffffffu, v, 1);
                if (l == 0) sred[w * 4 + rr] = v;
            }
            __syncthreads();   // bar3

            if (tid < ROWS_PER_CTA) {
                int g = tid >> 2, rr = tid & 3;
                float v = xv;
#pragma unroll
                for (int qq = 0; qq < 4; qq++)
                    v += sred[((qq << 2) | g) * 4 + rr];
#pragma unroll
                for (int r = 0; r < NREP; r++)
                    g_hrep[t & 1][r][r0 + tid] = v;
            }
        } else {
            if (tid < ROWS_PER_CTA) {
#pragma unroll
                for (int r = 0; r < NREP; r++)
                    g_hrep[0][r][r0 + tid] = xv;
            }
        }

        if (w == 0) {
            __syncwarp();
            if (l == 0) red_add_release(&g_cnt, 1u);
        }
    }

    // readout
    if (cta == 0) {
        if (w == 0) {
            const unsigned tgt = (unsigned)SEQ4 << 7;
            unsigned e;
            do { e = ld_relaxed(&g_cnt); }
            while (__any_sync(0xffffffffu, e < tgt));
            fence_acq();
        }
        __syncthreads();
        const float* hf = g_hrep[(SEQ4 - 1) & 1][0];
        float s = 0.f;
        for (int j = tid; j < HID; j += RTHREADS) s += __ldcg(&hf[j]) * Wh2o[j];
#pragma unroll
        for (int o = 16; o > 0; o >>= 1) s += __shfl_xor_sync(0xffffffffu, s, o);
        __syncthreads();
        if (l == 0) sred[w] = s;
        __syncthreads();
        if (tid == 0) {
            float tot = 0.f;
#pragma unroll
            for (int i = 0; i < RTHREADS / 32; i++) tot += sred[i];
            tot += bh2o[0];
            out[0] = 1.f / (1.f + expf(-tot));
        }
    }
}

// ---------------- launch ---------------------------------------------------
extern "C" void kernel_launch(void* const* d_in, const int* in_sizes, int n_in,
                              void* d_out, int out_size) {
    const int*   toks = (const int*)d_in[0];
    const float* emb  = (const float*)d_in[1];
    const float* Wi2h = (const float*)d_in[2];
    const float* bi2h = (const float*)d_in[3];
    const float* Wh2o = (const float*)d_in[4];
    const float* bh2o = (const float*)d_in[5];
    float* out = (float*)d_out;

    float* gX2; cudaGetSymbolAddress((void**)&gX2, g_X2);
    float* gX4; cudaGetSymbolAddress((void**)&gX4, g_X4);
    float* gW2; cudaGetSymbolAddress((void**)&gW2, g_W2);
    float* gW4; cudaGetSymbolAddress((void**)&gW4, g_W4);
    float* gX;  cudaGetSymbolAddress((void**)&gX,  g_X);

    reset_kernel<<<1, 32>>>();
    detect_tok_kernel<<<1, 256>>>(toks);
    gemm_x_kernel<<<dim3(HID / BN, SEQ / BM), GTHREADS>>>(toks, emb, Wi2h, bi2h);
    gemm_sq_kernel<WSTRIDE, EMB><<<dim3(HID / BN, HID / BM), GTHREADS>>>(Wi2h, gW2);
    gemm_fold_kernel<WSTRIDE, EMB><<<dim3(HID / BN, SEQ2 / BM), GTHREADS>>>(Wi2h, gX, gX2);
    gemm_sq_kernel<HID, 0><<<dim3(HID / BN, HID / BM), GTHREADS>>>(gW2, gW4);
    gemm_fold_kernel<HID, 0><<<dim3(HID / BN, SEQ4 / BM), GTHREADS>>>(gW2, gX2, gX4);
    rnn_kernel<<<NCTA, RTHREADS>>>(Wh2o, bh2o, out);
}